// round 16
// baseline (speedup 1.0000x reference)
#include <cuda_runtime.h>
#include <math.h>

#define NPTS 16384
#define NSP  4096
#define KNN  11
#define BT   64
#define WPB  (BT / 32)                // 2 points (warps) per block
#define FULLM 0xFFFFFFFFu

#define GRID  16
#define NCELL (GRID * GRID * GRID)    // 4096
#define CLO   (-4.0f)
#define CH    (0.5f)
#define INVCH (2.0f)
#define FINF  __int_as_float(0x7f800000)
#define NITEM (2 * NSP + 2 * NPTS)    // 40960 total items to bin

// Scratch (static __device__ arrays: allowed; no allocation)
__device__ float4 g_pts[2][NSP];          // binned spoints: (-2x,-2y,-2z,|s|^2)
__device__ int    g_oid[2][NSP];          // original spoint index per binned entry
__device__ int    g_cs [2][NCELL + 1];    // CSR cell starts (spoints)
__device__ int    g_qid[2][NPTS];         // query ids sorted by cell
__device__ int    g_cnt[4][NCELL];        // counters -> starts -> scatter cursors

__device__ __forceinline__ int clampi(int v, int lo, int hi) {
    return v < lo ? lo : (v > hi ? hi : v);
}
__device__ __forceinline__ int cell1d(float v) {
    return clampi((int)floorf((v - CLO) * INVCH), 0, GRID - 1);
}

// Monotone float->uint mapping (order-preserving for all finite floats)
__device__ __forceinline__ unsigned fkey(float f) {
    unsigned b = __float_as_uint(f);
    return b ^ ((unsigned)((int)b >> 31) | 0x80000000u);
}
__device__ __forceinline__ float funkey(unsigned u) {
    unsigned b = (u & 0x80000000u) ? (u ^ 0x80000000u) : ~u;
    return __uint_as_float(b);
}
#define SENTINEL 0xFF800000FFFFFFFFull   // upper = fkey(+inf)

// One-axis clamped distance of p to cell [lo, lo+CH)
__device__ __forceinline__ float axdist(float lo, float p) {
    return fmaxf(0.0f, fmaxf(lo - p, p - (lo + CH)));
}

// Map flat item index -> (slot, j, src base).
__device__ __forceinline__ void item_decode(
    int i, const float* sp, const float* pts,
    int& slot, int& j, const float*& src)
{
    if (i < 2 * NSP) {
        int b = i >> 12;
        slot = b;
        j = i & (NSP - 1);
        src = sp + (size_t)b * NSP * 3;
    } else {
        int k = i - 2 * NSP;
        int b = k >> 14;
        slot = 2 + b;
        j = k & (NPTS - 1);
        src = pts + (size_t)b * NPTS * 3;
    }
}

// ---------------------------------------------------------------------------
// Prep stage 1: count (g_cnt zeroed by memsetAsync)
// ---------------------------------------------------------------------------
__global__ void __launch_bounds__(256) count_kernel(
    const float* __restrict__ spoints, const float* __restrict__ points)
{
    const int i = blockIdx.x * 256 + threadIdx.x;
    if (i >= NITEM) return;
    int slot, j; const float* src;
    item_decode(i, spoints, points, slot, j, src);
    int cx = cell1d(src[3 * j + 0]);
    int cy = cell1d(src[3 * j + 1]);
    int cz = cell1d(src[3 * j + 2]);
    atomicAdd(&g_cnt[slot][(cz * GRID + cy) * GRID + cx], 1);
}

// ---------------------------------------------------------------------------
// Prep stage 2: per-slot exclusive scan (4 blocks, one per slot).
// ---------------------------------------------------------------------------
__global__ void __launch_bounds__(1024) scan_kernel() {
    const int slot = blockIdx.x;
    const int t    = threadIdx.x;
    const int lane = t & 31;
    const int wid  = t >> 5;
    int* cnt = g_cnt[slot];

    __shared__ int wsum[32];

    int v0 = cnt[t * 4 + 0], v1 = cnt[t * 4 + 1];
    int v2 = cnt[t * 4 + 2], v3 = cnt[t * 4 + 3];
    int s = v0 + v1 + v2 + v3;

    int x = s;
#pragma unroll
    for (int off = 1; off < 32; off <<= 1) {
        int y = __shfl_up_sync(FULLM, x, off);
        if (lane >= off) x += y;
    }
    if (lane == 31) wsum[wid] = x;
    __syncthreads();
    if (wid == 0) {
        int w = wsum[lane];
#pragma unroll
        for (int off = 1; off < 32; off <<= 1) {
            int y = __shfl_up_sync(FULLM, w, off);
            if (lane >= off) w += y;
        }
        wsum[lane] = w;
    }
    __syncthreads();
    int base = x - s + (wid ? wsum[wid - 1] : 0);

    int st0 = base;
    int st1 = st0 + v0;
    int st2 = st1 + v1;
    int st3 = st2 + v2;
    cnt[t * 4 + 0] = st0;
    cnt[t * 4 + 1] = st1;
    cnt[t * 4 + 2] = st2;
    cnt[t * 4 + 3] = st3;

    if (slot < 2) {
        g_cs[slot][t * 4 + 0] = st0;
        g_cs[slot][t * 4 + 1] = st1;
        g_cs[slot][t * 4 + 2] = st2;
        g_cs[slot][t * 4 + 3] = st3;
        if (t == 0) g_cs[slot][NCELL] = NSP;
    }
}

// ---------------------------------------------------------------------------
// Prep stage 3: scatter
// ---------------------------------------------------------------------------
__global__ void __launch_bounds__(256) scatter_kernel(
    const float* __restrict__ spoints, const float* __restrict__ points)
{
    const int i = blockIdx.x * 256 + threadIdx.x;
    if (i >= NITEM) return;
    int slot, j; const float* src;
    item_decode(i, spoints, points, slot, j, src);
    float x = src[3 * j + 0];
    float y = src[3 * j + 1];
    float z = src[3 * j + 2];
    int c = (cell1d(z) * GRID + cell1d(y)) * GRID + cell1d(x);
    int pos = atomicAdd(&g_cnt[slot][c], 1);
    if (slot < 2) {
        g_pts[slot][pos] = make_float4(-2.0f * x, -2.0f * y, -2.0f * z,
                                       fmaf(x, x, fmaf(y, y, z * z)));
        g_oid[slot][pos] = j;
    } else {
        g_qid[slot - 2][pos] = j;
    }
}

// ---------------------------------------------------------------------------
// Kernel 2: warp-per-point exact 11-NN, lane-distributed sorted top-11.
// Ring enumeration with HOISTED bound terms: dx^2 per ring, dz^2 per slice,
// dy^2 per row (identical pruning arithmetic, regrouped).
// ---------------------------------------------------------------------------
__global__ void __launch_bounds__(BT) voro_kernel(
    const float* __restrict__ points,
    const float* __restrict__ spoints,
    float* __restrict__ out)
{
    const int lane = threadIdx.x & 31;
    const int gp   = blockIdx.x * WPB + (threadIdx.x >> 5);  // sorted slot
    const int b    = gp >> 14;                               // gp / NPTS
    const int q    = g_qid[b][gp & (NPTS - 1)];              // original query id

    const float* pp = points + ((size_t)b * NPTS + q) * 3;
    const float px = pp[0], py = pp[1], pz = pp[2];          // warp-uniform
    const float p2 = fmaf(px, px, fmaf(py, py, pz * pz));

    const float4* __restrict__ pts = g_pts[b];
    const int*    __restrict__ oid = g_oid[b];
    const int*    __restrict__ cs  = g_cs[b];

    const int cx = cell1d(px), cy = cell1d(py), cz = cell1d(pz);

    // Distributed sorted top-11: lane k (k<11) holds element k.
    unsigned long long v = SENTINEL;
    float worst_e  = FINF;    // e-value of element 10 (e = |s|^2 - 2 p.s)
    float worst_d2 = FINF;

#define SCAN_RANGE(c0, c1)                                                    \
    {                                                                         \
        const int _s0 = __ldg(&cs[(c0)]);                                     \
        const int _s1 = __ldg(&cs[(c1) + 1]);                                 \
        for (int _base = _s0; _base < _s1; _base += 32) {                     \
            const int _idx = _base + lane;                                    \
            float _e = FINF;                                                  \
            unsigned _o = 0;                                                  \
            if (_idx < _s1) {                                                 \
                float4 _q = __ldg(&pts[_idx]);                                \
                _o = (unsigned)__ldg(&oid[_idx]);   /* eager: hidden latency */\
                _e = fmaf(_q.x, px, fmaf(_q.y, py, fmaf(_q.z, pz, _q.w)));    \
            }                                                                 \
            unsigned _act = __ballot_sync(FULLM,                              \
                                          (_idx < _s1) && (_e <= worst_e));   \
            if (_act) {                                                       \
                unsigned long long _key =                                     \
                    ((unsigned long long)fkey(_e) << 32) | _o;                \
                do {                                                          \
                    int _src = __ffs(_act) - 1;                               \
                    _act &= _act - 1;                                         \
                    unsigned long long _k = __shfl_sync(FULLM, _key, _src);   \
                    unsigned long long _vp = __shfl_up_sync(FULLM, v, 1);     \
                    int _pos = __popc(__ballot_sync(FULLM, v < _k) & 0x7FFu); \
                    if (lane < KNN) {                                         \
                        if (lane == _pos) v = _k;                             \
                        else if (lane > _pos) v = _vp;                        \
                    }                                                         \
                } while (_act);                                               \
                unsigned long long _w = __shfl_sync(FULLM, v, KNN - 1);       \
                worst_e  = funkey((unsigned)(_w >> 32));                      \
                worst_d2 = worst_e + p2;                                      \
            }                                                                 \
        }                                                                     \
    }

// Row with precomputed (dy^2+dz^2) and dx^2 terms
#define ROWB(zz, yy, xa, xb, dyz2, dxx2)                                      \
    if (((dyz2) + (dxx2)) * 0.99999f <= worst_d2) {                           \
        const int _rb = ((zz) * GRID + (yy)) * GRID;                          \
        SCAN_RANGE(_rb + (xa), _rb + (xb));                                   \
    }

    // Ring 0: own cell
    {
        const int c = (cz * GRID + cy) * GRID + cx;
        SCAN_RANGE(c, c);
    }

    for (int r = 0; ; ++r) {
        // Termination: min possible distance to any cell beyond the cube.
        float m = FINF;
        if (cx - r > 0)        m = fminf(m, px - (CLO + (cx - r) * CH));
        if (cx + r < GRID - 1) m = fminf(m, (CLO + (cx + r + 1) * CH) - px);
        if (cy - r > 0)        m = fminf(m, py - (CLO + (cy - r) * CH));
        if (cy + r < GRID - 1) m = fminf(m, (CLO + (cy + r + 1) * CH) - py);
        if (cz - r > 0)        m = fminf(m, pz - (CLO + (cz - r) * CH));
        if (cz + r < GRID - 1) m = fminf(m, (CLO + (cz + r + 1) * CH) - pz);
        m = fmaxf(m, 0.0f);
        if (worst_d2 <= m * m * 0.99999f) break;
        if (r >= GRID - 1) break;

        const int rr = r + 1;
        const int x0 = max(cx - rr, 0), x1 = min(cx + rr, GRID - 1);
        const int y0 = max(cy - rr, 0), y1 = min(cy + rr, GRID - 1);
        const int zi0 = max(cz - rr + 1, 0), zi1 = min(cz + rr - 1, GRID - 1);
        const int yi0 = max(cy - rr + 1, 0), yi1 = min(cy + rr - 1, GRID - 1);

        // Ring-level hoists: dx^2 for the full x-span and the two x-sides.
        float dxs  = fmaxf(0.0f, fmaxf((CLO + x0 * CH) - px,
                                       px - (CLO + (x1 + 1) * CH)));
        float dxs2 = dxs * dxs;
        float dl   = axdist(CLO + (cx - rr) * CH, px);
        float dxl2 = dl * dl;
        float dh   = axdist(CLO + (cx + rr) * CH, px);
        float dxh2 = dh * dh;

        // z-faces: full rows
        if (cz - rr >= 0) {
            float dz = axdist(CLO + (cz - rr) * CH, pz);
            float dz2 = dz * dz;
            for (int yy = y0; yy <= y1; ++yy) {
                float dy = axdist(CLO + yy * CH, py);
                float dyz2 = fmaf(dy, dy, dz2);
                ROWB(cz - rr, yy, x0, x1, dyz2, dxs2);
            }
        }
        if (cz + rr <= GRID - 1) {
            float dz = axdist(CLO + (cz + rr) * CH, pz);
            float dz2 = dz * dz;
            for (int yy = y0; yy <= y1; ++yy) {
                float dy = axdist(CLO + yy * CH, py);
                float dyz2 = fmaf(dy, dy, dz2);
                ROWB(cz + rr, yy, x0, x1, dyz2, dxs2);
            }
        }
        // interior z slices: y-face rows + x-side single cells
        for (int zz = zi0; zz <= zi1; ++zz) {
            float dz = axdist(CLO + zz * CH, pz);
            float dz2 = dz * dz;
            if (cy - rr >= 0) {
                float dy = axdist(CLO + (cy - rr) * CH, py);
                float dyz2 = fmaf(dy, dy, dz2);
                ROWB(zz, cy - rr, x0, x1, dyz2, dxs2);
            }
            if (cy + rr <= GRID - 1) {
                float dy = axdist(CLO + (cy + rr) * CH, py);
                float dyz2 = fmaf(dy, dy, dz2);
                ROWB(zz, cy + rr, x0, x1, dyz2, dxs2);
            }
            for (int yy = yi0; yy <= yi1; ++yy) {
                float dy = axdist(CLO + yy * CH, py);
                float dyz2 = fmaf(dy, dy, dz2);
                if (cx - rr >= 0)        ROWB(zz, yy, cx - rr, cx - rr, dyz2, dxl2);
                if (cx + rr <= GRID - 1) ROWB(zz, yy, cx + rr, cx + rr, dyz2, dxh2);
            }
        }
    }
#undef ROWB
#undef SCAN_RANGE

    // Epilogue: lane k holds neighbor k. Lanes 1..10 compute one Voronoi edge
    // each: sq = (dot(v,e) - |e|^2/2)^2 / |e|^2; warp-min reduce.
    const float* sp = spoints + (size_t)b * NSP * 3;
    const unsigned long long v0 = __shfl_sync(FULLM, v, 0);
    const int i0 = (int)(v0 & 0xFFFFFFFFull);
    const float cx0 = __ldg(sp + 3 * i0 + 0);   // broadcast
    const float cy0 = __ldg(sp + 3 * i0 + 1);
    const float cz0 = __ldg(sp + 3 * i0 + 2);

    float val = FINF;
    if (lane >= 1 && lane < KNN) {
        const int ik = (int)(v & 0xFFFFFFFFull);
        float ex = __ldg(sp + 3 * ik + 0) - cx0;
        float ey = __ldg(sp + 3 * ik + 1) - cy0;
        float ez = __ldg(sp + 3 * ik + 2) - cz0;
        float vx = px - cx0, vy = py - cy0, vz = pz - cz0;
        float el2 = fmaf(ex, ex, fmaf(ey, ey, ez * ez));
        float dve = fmaf(vx, ex, fmaf(vy, ey, vz * ez));
        float u   = fmaf(-0.5f, el2, dve);
        val = (u * u) / el2;
    }
#pragma unroll
    for (int off = 16; off; off >>= 1)
        val = fminf(val, __shfl_xor_sync(FULLM, val, off));

    if (lane == 0) out[(size_t)b * NPTS + q] = val;
}

extern "C" void kernel_launch(void* const* d_in, const int* in_sizes, int n_in,
                              void* d_out, int out_size) {
    const float* points  = (const float*)d_in[0];   // (2, 16384, 3) f32
    const float* spoints = (const float*)d_in[1];   // (2, 4096, 3)  f32
    float* out = (float*)d_out;                     // (2, 16384)    f32

    void* cnt_ptr = nullptr;
    cudaGetSymbolAddress(&cnt_ptr, g_cnt);
    cudaMemsetAsync(cnt_ptr, 0, sizeof(int) * 4 * NCELL);

    const int nb = (NITEM + 255) / 256;
    count_kernel<<<nb, 256>>>(spoints, points);
    scan_kernel<<<4, 1024>>>();
    scatter_kernel<<<nb, 256>>>(spoints, points);
    voro_kernel<<<(2 * NPTS) / WPB, BT>>>(points, spoints, out);
}

// round 17
// speedup vs baseline: 1.0240x; 1.0240x over previous
#include <cuda_runtime.h>
#include <math.h>

#define NPTS 16384
#define NSP  4096
#define KNN  11
#define BT   64
#define WPB  (BT / 32)                // 2 points (warps) per block
#define FULLM 0xFFFFFFFFu

#define GRID  16
#define NCELL (GRID * GRID * GRID)    // 4096
#define CLO   (-4.0f)
#define CH    (0.5f)
#define INVCH (2.0f)
#define FINF  __int_as_float(0x7f800000)
#define NITEM (2 * NSP + 2 * NPTS)    // 40960 total items to bin

// Scratch (static __device__ arrays: allowed; no allocation)
__device__ float4 g_pts[2][NSP];          // binned spoints: (-2x,-2y,-2z,|s|^2)
__device__ int    g_oid[2][NSP];          // original spoint index per binned entry
__device__ int    g_cs [2][NCELL + 1];    // CSR cell starts (spoints)
__device__ int    g_qid[2][NPTS];         // query ids sorted by cell
__device__ int    g_cnt[4][NCELL];        // counters -> starts -> scatter cursors

__device__ __forceinline__ int clampi(int v, int lo, int hi) {
    return v < lo ? lo : (v > hi ? hi : v);
}
__device__ __forceinline__ int cell1d(float v) {
    return clampi((int)floorf((v - CLO) * INVCH), 0, GRID - 1);
}

// Monotone float->uint mapping (order-preserving for all finite floats)
__device__ __forceinline__ unsigned fkey(float f) {
    unsigned b = __float_as_uint(f);
    return b ^ ((unsigned)((int)b >> 31) | 0x80000000u);
}
__device__ __forceinline__ float funkey(unsigned u) {
    unsigned b = (u & 0x80000000u) ? (u ^ 0x80000000u) : ~u;
    return __uint_as_float(b);
}
#define SENTINEL 0xFF800000FFFFFFFFull   // upper = fkey(+inf)

// Map flat item index -> (slot, j, src base).
__device__ __forceinline__ void item_decode(
    int i, const float* sp, const float* pts,
    int& slot, int& j, const float*& src)
{
    if (i < 2 * NSP) {
        int b = i >> 12;
        slot = b;
        j = i & (NSP - 1);
        src = sp + (size_t)b * NSP * 3;
    } else {
        int k = i - 2 * NSP;
        int b = k >> 14;
        slot = 2 + b;
        j = k & (NPTS - 1);
        src = pts + (size_t)b * NPTS * 3;
    }
}

// ---------------------------------------------------------------------------
// Prep stage 1: count (g_cnt zeroed by memsetAsync)
// ---------------------------------------------------------------------------
__global__ void __launch_bounds__(256) count_kernel(
    const float* __restrict__ spoints, const float* __restrict__ points)
{
    const int i = blockIdx.x * 256 + threadIdx.x;
    if (i >= NITEM) return;
    int slot, j; const float* src;
    item_decode(i, spoints, points, slot, j, src);
    int cx = cell1d(src[3 * j + 0]);
    int cy = cell1d(src[3 * j + 1]);
    int cz = cell1d(src[3 * j + 2]);
    atomicAdd(&g_cnt[slot][(cz * GRID + cy) * GRID + cx], 1);
}

// ---------------------------------------------------------------------------
// Prep stage 2: per-slot exclusive scan (4 blocks, one per slot).
// ---------------------------------------------------------------------------
__global__ void __launch_bounds__(1024) scan_kernel() {
    const int slot = blockIdx.x;
    const int t    = threadIdx.x;
    const int lane = t & 31;
    const int wid  = t >> 5;
    int* cnt = g_cnt[slot];

    __shared__ int wsum[32];

    int v0 = cnt[t * 4 + 0], v1 = cnt[t * 4 + 1];
    int v2 = cnt[t * 4 + 2], v3 = cnt[t * 4 + 3];
    int s = v0 + v1 + v2 + v3;

    int x = s;
#pragma unroll
    for (int off = 1; off < 32; off <<= 1) {
        int y = __shfl_up_sync(FULLM, x, off);
        if (lane >= off) x += y;
    }
    if (lane == 31) wsum[wid] = x;
    __syncthreads();
    if (wid == 0) {
        int w = wsum[lane];
#pragma unroll
        for (int off = 1; off < 32; off <<= 1) {
            int y = __shfl_up_sync(FULLM, w, off);
            if (lane >= off) w += y;
        }
        wsum[lane] = w;
    }
    __syncthreads();
    int base = x - s + (wid ? wsum[wid - 1] : 0);

    int st0 = base;
    int st1 = st0 + v0;
    int st2 = st1 + v1;
    int st3 = st2 + v2;
    cnt[t * 4 + 0] = st0;
    cnt[t * 4 + 1] = st1;
    cnt[t * 4 + 2] = st2;
    cnt[t * 4 + 3] = st3;

    if (slot < 2) {
        g_cs[slot][t * 4 + 0] = st0;
        g_cs[slot][t * 4 + 1] = st1;
        g_cs[slot][t * 4 + 2] = st2;
        g_cs[slot][t * 4 + 3] = st3;
        if (t == 0) g_cs[slot][NCELL] = NSP;
    }
}

// ---------------------------------------------------------------------------
// Prep stage 3: scatter
// ---------------------------------------------------------------------------
__global__ void __launch_bounds__(256) scatter_kernel(
    const float* __restrict__ spoints, const float* __restrict__ points)
{
    const int i = blockIdx.x * 256 + threadIdx.x;
    if (i >= NITEM) return;
    int slot, j; const float* src;
    item_decode(i, spoints, points, slot, j, src);
    float x = src[3 * j + 0];
    float y = src[3 * j + 1];
    float z = src[3 * j + 2];
    int c = (cell1d(z) * GRID + cell1d(y)) * GRID + cell1d(x);
    int pos = atomicAdd(&g_cnt[slot][c], 1);
    if (slot < 2) {
        g_pts[slot][pos] = make_float4(-2.0f * x, -2.0f * y, -2.0f * z,
                                       fmaf(x, x, fmaf(y, y, z * z)));
        g_oid[slot][pos] = j;
    } else {
        g_qid[slot - 2][pos] = j;
    }
}

// ---------------------------------------------------------------------------
// Kernel 2: warp-per-point exact 11-NN, lane-distributed sorted top-11
// (lane k holds element k; insert = ballot+popc+shfl_up). Eager oid load,
// deferred worst refresh. BT=64 for balance. (Exact R13 configuration —
// the fastest measured variant: 103.5 us.)
// ---------------------------------------------------------------------------
__global__ void __launch_bounds__(BT) voro_kernel(
    const float* __restrict__ points,
    const float* __restrict__ spoints,
    float* __restrict__ out)
{
    const int lane = threadIdx.x & 31;
    const int gp   = blockIdx.x * WPB + (threadIdx.x >> 5);  // sorted slot
    const int b    = gp >> 14;                               // gp / NPTS
    const int q    = g_qid[b][gp & (NPTS - 1)];              // original query id

    const float* pp = points + ((size_t)b * NPTS + q) * 3;
    const float px = pp[0], py = pp[1], pz = pp[2];          // warp-uniform
    const float p2 = fmaf(px, px, fmaf(py, py, pz * pz));

    const float4* __restrict__ pts = g_pts[b];
    const int*    __restrict__ oid = g_oid[b];
    const int*    __restrict__ cs  = g_cs[b];

    const int cx = cell1d(px), cy = cell1d(py), cz = cell1d(pz);

    // Distributed sorted top-11: lane k (k<11) holds element k.
    unsigned long long v = SENTINEL;
    float worst_e  = FINF;    // e-value of element 10 (e = |s|^2 - 2 p.s)
    float worst_d2 = FINF;

    // Insert position = popc(ballot(v < key) & 0x7FF): exact from the list
    // itself; key >= all 11 entries -> pos >= 11 -> automatic no-op. The
    // worst_e filter being one batch stale only admits extra no-op inserts.
#define SCAN_RANGE(c0, c1)                                                    \
    {                                                                         \
        const int _s0 = __ldg(&cs[(c0)]);                                     \
        const int _s1 = __ldg(&cs[(c1) + 1]);                                 \
        for (int _base = _s0; _base < _s1; _base += 32) {                     \
            const int _idx = _base + lane;                                    \
            float _e = FINF;                                                  \
            unsigned _o = 0;                                                  \
            if (_idx < _s1) {                                                 \
                float4 _q = __ldg(&pts[_idx]);                                \
                _o = (unsigned)__ldg(&oid[_idx]);   /* eager: hidden latency */\
                _e = fmaf(_q.x, px, fmaf(_q.y, py, fmaf(_q.z, pz, _q.w)));    \
            }                                                                 \
            unsigned _act = __ballot_sync(FULLM,                              \
                                          (_idx < _s1) && (_e <= worst_e));   \
            if (_act) {                                                       \
                unsigned long long _key =                                     \
                    ((unsigned long long)fkey(_e) << 32) | _o;                \
                do {                                                          \
                    int _src = __ffs(_act) - 1;                               \
                    _act &= _act - 1;                                         \
                    unsigned long long _k = __shfl_sync(FULLM, _key, _src);   \
                    unsigned long long _vp = __shfl_up_sync(FULLM, v, 1);     \
                    int _pos = __popc(__ballot_sync(FULLM, v < _k) & 0x7FFu); \
                    if (lane < KNN) {                                         \
                        if (lane == _pos) v = _k;                             \
                        else if (lane > _pos) v = _vp;                        \
                    }                                                         \
                } while (_act);                                               \
                unsigned long long _w = __shfl_sync(FULLM, v, KNN - 1);       \
                worst_e  = funkey((unsigned)(_w >> 32));                      \
                worst_d2 = worst_e + p2;                                      \
            }                                                                 \
        }                                                                     \
    }

#define ROW(zz, yy, xa, xb)                                                   \
    {                                                                         \
        float _lo, _dx, _dy, _dz;                                             \
        _lo = CLO + (xa) * CH;                                                \
        _dx = fmaxf(0.0f, fmaxf(_lo - px, px - (CLO + ((xb) + 1) * CH)));     \
        _lo = CLO + (yy) * CH;                                                \
        _dy = fmaxf(0.0f, fmaxf(_lo - py, py - (_lo + CH)));                  \
        _lo = CLO + (zz) * CH;                                                \
        _dz = fmaxf(0.0f, fmaxf(_lo - pz, pz - (_lo + CH)));                  \
        float _d2c = fmaf(_dx, _dx, fmaf(_dy, _dy, _dz * _dz));               \
        if (_d2c * 0.99999f <= worst_d2) {                                    \
            const int _rb = ((zz) * GRID + (yy)) * GRID;                      \
            SCAN_RANGE(_rb + (xa), _rb + (xb));                               \
        }                                                                     \
    }

    // Ring 0: own cell
    {
        const int c = (cz * GRID + cy) * GRID + cx;
        SCAN_RANGE(c, c);
    }

    for (int r = 0; ; ++r) {
        // Min possible distance to any cell beyond the scanned cube; faces
        // clipped at the grid edge contribute +inf (candidates clamped inside).
        float m = FINF;
        if (cx - r > 0)        m = fminf(m, px - (CLO + (cx - r) * CH));
        if (cx + r < GRID - 1) m = fminf(m, (CLO + (cx + r + 1) * CH) - px);
        if (cy - r > 0)        m = fminf(m, py - (CLO + (cy - r) * CH));
        if (cy + r < GRID - 1) m = fminf(m, (CLO + (cy + r + 1) * CH) - py);
        if (cz - r > 0)        m = fminf(m, pz - (CLO + (cz - r) * CH));
        if (cz + r < GRID - 1) m = fminf(m, (CLO + (cz + r + 1) * CH) - pz);
        m = fmaxf(m, 0.0f);
        if (worst_d2 <= m * m * 0.99999f) break;
        if (r >= GRID - 1) break;

        const int rr = r + 1;
        const int x0 = max(cx - rr, 0), x1 = min(cx + rr, GRID - 1);
        const int y0 = max(cy - rr, 0), y1 = min(cy + rr, GRID - 1);
        const int zi0 = max(cz - rr + 1, 0), zi1 = min(cz + rr - 1, GRID - 1);
        const int yi0 = max(cy - rr + 1, 0), yi1 = min(cy + rr - 1, GRID - 1);

        if (cz - rr >= 0)
            for (int yy = y0; yy <= y1; ++yy) ROW(cz - rr, yy, x0, x1);
        if (cz + rr <= GRID - 1)
            for (int yy = y0; yy <= y1; ++yy) ROW(cz + rr, yy, x0, x1);
        for (int zz = zi0; zz <= zi1; ++zz) {
            if (cy - rr >= 0)          ROW(zz, cy - rr, x0, x1);
            if (cy + rr <= GRID - 1)   ROW(zz, cy + rr, x0, x1);
            for (int yy = yi0; yy <= yi1; ++yy) {
                if (cx - rr >= 0)        ROW(zz, yy, cx - rr, cx - rr);
                if (cx + rr <= GRID - 1) ROW(zz, yy, cx + rr, cx + rr);
            }
        }
    }
#undef ROW
#undef SCAN_RANGE

    // Epilogue: lane k holds neighbor k. Lanes 1..10 compute one Voronoi edge
    // each: sq = (dot(v,e) - |e|^2/2)^2 / |e|^2; warp-min reduce.
    const float* sp = spoints + (size_t)b * NSP * 3;
    const unsigned long long v0 = __shfl_sync(FULLM, v, 0);
    const int i0 = (int)(v0 & 0xFFFFFFFFull);
    const float cx0 = __ldg(sp + 3 * i0 + 0);   // broadcast
    const float cy0 = __ldg(sp + 3 * i0 + 1);
    const float cz0 = __ldg(sp + 3 * i0 + 2);

    float val = FINF;
    if (lane >= 1 && lane < KNN) {
        const int ik = (int)(v & 0xFFFFFFFFull);
        float ex = __ldg(sp + 3 * ik + 0) - cx0;
        float ey = __ldg(sp + 3 * ik + 1) - cy0;
        float ez = __ldg(sp + 3 * ik + 2) - cz0;
        float vx = px - cx0, vy = py - cy0, vz = pz - cz0;
        float el2 = fmaf(ex, ex, fmaf(ey, ey, ez * ez));
        float dve = fmaf(vx, ex, fmaf(vy, ey, vz * ez));
        float u   = fmaf(-0.5f, el2, dve);
        val = (u * u) / el2;
    }
#pragma unroll
    for (int off = 16; off; off >>= 1)
        val = fminf(val, __shfl_xor_sync(FULLM, val, off));

    if (lane == 0) out[(size_t)b * NPTS + q] = val;
}

extern "C" void kernel_launch(void* const* d_in, const int* in_sizes, int n_in,
                              void* d_out, int out_size) {
    const float* points  = (const float*)d_in[0];   // (2, 16384, 3) f32
    const float* spoints = (const float*)d_in[1];   // (2, 4096, 3)  f32
    float* out = (float*)d_out;                     // (2, 16384)    f32

    void* cnt_ptr = nullptr;
    cudaGetSymbolAddress(&cnt_ptr, g_cnt);
    cudaMemsetAsync(cnt_ptr, 0, sizeof(int) * 4 * NCELL);

    const int nb = (NITEM + 255) / 256;
    count_kernel<<<nb, 256>>>(spoints, points);
    scan_kernel<<<4, 1024>>>();
    scatter_kernel<<<nb, 256>>>(spoints, points);
    voro_kernel<<<(2 * NPTS) / WPB, BT>>>(points, spoints, out);
}